// round 1
// baseline (speedup 1.0000x reference)
#include <cuda_runtime.h>
#include <math.h>

#define NROWS 32768
#define DDIM  256
#define EPSV  1e-5f

// Scratch (allocation-free rule: __device__ globals)
__device__ float g_Y1[NROWS * DDIM];
__device__ float g_Y2[NROWS * DDIM];
__device__ float g_sum  [3 * DDIM];
__device__ float g_sumsq[3 * DDIM];
__device__ float g_scale[3 * DDIM];
__device__ float g_shift[3 * DDIM];

__global__ void zero_stats_kernel() {
    int i = blockIdx.x * blockDim.x + threadIdx.x;
    if (i < 3 * DDIM) { g_sum[i] = 0.f; g_sumsq[i] = 0.f; }
}

__global__ void finalize_stats_kernel(int layer,
                                      const float* __restrict__ g,
                                      const float* __restrict__ be) {
    int c = threadIdx.x;  // 256 threads
    const float inv = 1.0f / (float)NROWS;
    float mu  = g_sum  [layer * DDIM + c] * inv;
    float var = g_sumsq[layer * DDIM + c] * inv - mu * mu;
    float s = rsqrtf(var + EPSV) * g[c];
    g_scale[layer * DDIM + c] = s;
    g_shift[layer * DDIM + c] = be[c] - mu * s;
}

__device__ __forceinline__ float gelu_exact(float x) {
    return 0.5f * x * (1.0f + erff(x * 0.70710678118654752440f));
}

// One fused layer: out = GELU( A' @ W + bias ), A' = gather(table, ids) (layer 1)
// or A' = A * scale + shift (BN folded into load, layers 2-4).
// Optionally accumulates per-column sum / sumsq for the next BN.
// 128x128 tile, BK=16, 256 threads, 8x8 per-thread (4+4 split each dim).
template<int GATHER, int USEBN, int STATS>
__global__ __launch_bounds__(256, 2)
void layer_kernel(const float* __restrict__ A,
                  const int*   __restrict__ ids,
                  const float* __restrict__ table,
                  const float* __restrict__ W,
                  const float* __restrict__ bias,
                  int layer,
                  float* __restrict__ out)
{
    __shared__ float As[16][132];   // k-major, padded (stride 132)
    __shared__ float Ws[16][128];
    __shared__ int   s_ids[128];
    __shared__ float red[16][128];

    const int tid = threadIdx.x;
    const int tx  = tid & 15;
    const int ty  = tid >> 4;
    const int r0  = blockIdx.x * 128;
    const int c0  = blockIdx.y * 128;

    const float* scale = g_scale + (layer - 1) * DDIM;  // only deref'd when USEBN
    const float* shift = g_shift + (layer - 1) * DDIM;

    if (GATHER) {
        if (tid < 128) s_ids[tid] = ids[r0 + tid];
        __syncthreads();
    }

    float acc[8][8];
    #pragma unroll
    for (int i = 0; i < 8; i++)
        #pragma unroll
        for (int j = 0; j < 8; j++) acc[i][j] = 0.f;

    for (int kt = 0; kt < DDIM; kt += 16) {
        // ---- A tile: 128 rows x 16 k, 512 float4, 2 per thread ----
        #pragma unroll
        for (int m = 0; m < 2; m++) {
            int f  = tid + m * 256;
            int r  = f >> 2;            // 0..127
            int kc = (f & 3) * 4;       // 0,4,8,12
            const float* src;
            if (GATHER) src = table + (size_t)s_ids[r] * DDIM + kt + kc;
            else        src = A + (size_t)(r0 + r) * DDIM + kt + kc;
            float4 v = *reinterpret_cast<const float4*>(src);
            if (USEBN) {
                v.x = fmaf(v.x, scale[kt + kc + 0], shift[kt + kc + 0]);
                v.y = fmaf(v.y, scale[kt + kc + 1], shift[kt + kc + 1]);
                v.z = fmaf(v.z, scale[kt + kc + 2], shift[kt + kc + 2]);
                v.w = fmaf(v.w, scale[kt + kc + 3], shift[kt + kc + 3]);
            }
            As[kc + 0][r] = v.x; As[kc + 1][r] = v.y;
            As[kc + 2][r] = v.z; As[kc + 3][r] = v.w;
        }
        // ---- W tile: 16 x 128, 512 float4, 2 per thread ----
        #pragma unroll
        for (int m = 0; m < 2; m++) {
            int f  = tid + m * 256;
            int kr = f >> 5;            // 0..15
            int cf = (f & 31) * 4;      // 0..124
            float4 v = *reinterpret_cast<const float4*>(
                W + (size_t)(kt + kr) * DDIM + c0 + cf);
            *reinterpret_cast<float4*>(&Ws[kr][cf]) = v;
        }
        __syncthreads();

        #pragma unroll
        for (int k = 0; k < 16; k++) {
            float4 a0 = *reinterpret_cast<const float4*>(&As[k][ty * 4]);
            float4 a1 = *reinterpret_cast<const float4*>(&As[k][64 + ty * 4]);
            float4 w0 = *reinterpret_cast<const float4*>(&Ws[k][tx * 4]);
            float4 w1 = *reinterpret_cast<const float4*>(&Ws[k][64 + tx * 4]);
            float a[8] = {a0.x, a0.y, a0.z, a0.w, a1.x, a1.y, a1.z, a1.w};
            float w[8] = {w0.x, w0.y, w0.z, w0.w, w1.x, w1.y, w1.z, w1.w};
            #pragma unroll
            for (int i = 0; i < 8; i++)
                #pragma unroll
                for (int j = 0; j < 8; j++)
                    acc[i][j] = fmaf(a[i], w[j], acc[i][j]);
        }
        __syncthreads();
    }

    // ---- epilogue: bias + exact GELU + store (+ column stats) ----
    float bcol[8];
    #pragma unroll
    for (int j = 0; j < 8; j++) {
        int cl = (j < 4) ? (tx * 4 + j) : (64 + tx * 4 + (j - 4));
        bcol[j] = bias[c0 + cl];
    }
    float csum[8], csq[8];
    #pragma unroll
    for (int j = 0; j < 8; j++) { csum[j] = 0.f; csq[j] = 0.f; }

    #pragma unroll
    for (int i = 0; i < 8; i++) {
        int r = r0 + ((i < 4) ? (ty * 4 + i) : (64 + ty * 4 + (i - 4)));
        float v[8];
        #pragma unroll
        for (int j = 0; j < 8; j++) {
            v[j] = gelu_exact(acc[i][j] + bcol[j]);
            if (STATS) { csum[j] += v[j]; csq[j] += v[j] * v[j]; }
        }
        float4 o0 = make_float4(v[0], v[1], v[2], v[3]);
        float4 o1 = make_float4(v[4], v[5], v[6], v[7]);
        *reinterpret_cast<float4*>(&out[(size_t)r * DDIM + c0 + tx * 4])      = o0;
        *reinterpret_cast<float4*>(&out[(size_t)r * DDIM + c0 + 64 + tx * 4]) = o1;
    }

    if (STATS) {
        #pragma unroll
        for (int j = 0; j < 8; j++) {
            int cl = (j < 4) ? (tx * 4 + j) : (64 + tx * 4 + (j - 4));
            red[ty][cl] = csum[j];
        }
        __syncthreads();
        if (tid < 128) {
            float s = 0.f;
            #pragma unroll
            for (int t = 0; t < 16; t++) s += red[t][tid];
            atomicAdd(&g_sum[layer * DDIM + c0 + tid], s);
        }
        __syncthreads();
        #pragma unroll
        for (int j = 0; j < 8; j++) {
            int cl = (j < 4) ? (tx * 4 + j) : (64 + tx * 4 + (j - 4));
            red[ty][cl] = csq[j];
        }
        __syncthreads();
        if (tid < 128) {
            float s = 0.f;
            #pragma unroll
            for (int t = 0; t < 16; t++) s += red[t][tid];
            atomicAdd(&g_sumsq[layer * DDIM + c0 + tid], s);
        }
    }
}

extern "C" void kernel_launch(void* const* d_in, const int* in_sizes, int n_in,
                              void* d_out, int out_size) {
    const int*   ids   = (const int*)  d_in[0];
    const float* table = (const float*)d_in[1];
    const float* W1 = (const float*)d_in[2];  const float* b1 = (const float*)d_in[3];
    const float* W2 = (const float*)d_in[4];  const float* b2 = (const float*)d_in[5];
    const float* W3 = (const float*)d_in[6];  const float* b3 = (const float*)d_in[7];
    const float* W4 = (const float*)d_in[8];  const float* b4 = (const float*)d_in[9];
    const float* g1 = (const float*)d_in[10]; const float* be1 = (const float*)d_in[11];
    const float* g2 = (const float*)d_in[12]; const float* be2 = (const float*)d_in[13];
    const float* g3 = (const float*)d_in[14]; const float* be3 = (const float*)d_in[15];
    float* out = (float*)d_out;

    float *Y1 = nullptr, *Y2 = nullptr;
    cudaGetSymbolAddress((void**)&Y1, g_Y1);
    cudaGetSymbolAddress((void**)&Y2, g_Y2);

    dim3 grid(NROWS / 128, DDIM / 128);  // 256 x 2 = 512 blocks
    dim3 blk(256);

    zero_stats_kernel<<<1, 768>>>();

    // L1: gather + GEMM + GELU + stats0
    layer_kernel<1, 0, 1><<<grid, blk>>>(nullptr, ids, table, W1, b1, 0, Y1);
    finalize_stats_kernel<<<1, 256>>>(0, g1, be1);

    // L2: BN0-on-load + GEMM + GELU + stats1
    layer_kernel<0, 1, 1><<<grid, blk>>>(Y1, nullptr, nullptr, W2, b2, 1, Y2);
    finalize_stats_kernel<<<1, 256>>>(1, g2, be2);

    // L3: BN1-on-load + GEMM + GELU + stats2
    layer_kernel<0, 1, 1><<<grid, blk>>>(Y2, nullptr, nullptr, W3, b3, 2, Y1);
    finalize_stats_kernel<<<1, 256>>>(2, g3, be3);

    // L4: BN2-on-load + GEMM + GELU -> d_out
    layer_kernel<0, 1, 0><<<grid, blk>>>(Y1, nullptr, nullptr, W4, b4, 3, out);
}

// round 3
// speedup vs baseline: 1.8378x; 1.8378x over previous
#include <cuda_runtime.h>
#include <cuda_bf16.h>
#include <math.h>
#include <stdint.h>

#define NROWS 32768
#define DDIM  256
#define EPSV  1e-5f
#define KC    64
#define STAGE_BYTES 98304        // Ahi 16K | Alo 16K | Bhi 32K | Blo 32K
#define SMEM_DYN (2 * STAGE_BYTES + 1024)

// ---------------- device scratch (no allocations allowed) ----------------
__device__ __nv_bfloat16 g_Xhi[NROWS * DDIM];
__device__ __nv_bfloat16 g_Xlo[NROWS * DDIM];
__device__ __nv_bfloat16 g_Yhi[NROWS * DDIM];
__device__ __nv_bfloat16 g_Ylo[NROWS * DDIM];
__device__ __nv_bfloat16 g_Bhi[4][DDIM * DDIM];   // B[n][k] = s_k * W[k][n], hi
__device__ __nv_bfloat16 g_Blo[4][DDIM * DDIM];
__device__ float g_bias [4][DDIM];                 // b'[n] = b[n] + sum_k t_k W[k][n]
__device__ float g_sum  [3 * DDIM];
__device__ float g_sumsq[3 * DDIM];
__device__ float g_scale[3 * DDIM];
__device__ float g_shift[3 * DDIM];

// ---------------- helpers ----------------
__device__ __forceinline__ uint32_t sm_u32(const void* p) {
    return (uint32_t)__cvta_generic_to_shared(p);
}
__device__ __forceinline__ float gelu_exact(float x) {
    return 0.5f * x * (1.0f + erff(x * 0.70710678118654752440f));
}
__device__ __forceinline__ void split2(float v, __nv_bfloat16& h, __nv_bfloat16& l) {
    h = __float2bfloat16(v);
    l = __float2bfloat16(v - __bfloat162float(h));
}
__device__ __forceinline__ uint32_t pack2(__nv_bfloat16 a, __nv_bfloat16 b) {
    __nv_bfloat162 t = __halves2bfloat162(a, b);
    return *reinterpret_cast<uint32_t*>(&t);
}
__device__ __forceinline__ uint32_t swz(uint32_t off) {
    return off ^ ((off >> 3) & 0x70);
}

#define CP16(sm, gp) \
    asm volatile("cp.async.cg.shared.global [%0], [%1], 16;" :: "r"(sm), "l"(gp) : "memory")
#define CP_COMMIT() asm volatile("cp.async.commit_group;" ::: "memory")
#define CP_WAIT1()  asm volatile("cp.async.wait_group 1;" ::: "memory")
#define CP_WAIT0()  asm volatile("cp.async.wait_group 0;" ::: "memory")

#define LDSM_X4(r, addr) \
    asm volatile("ldmatrix.sync.aligned.m8n8.x4.shared.b16 {%0,%1,%2,%3}, [%4];" \
        : "=r"((r)[0]), "=r"((r)[1]), "=r"((r)[2]), "=r"((r)[3]) : "r"(addr))
#define LDSM_X2(r0, r1, addr) \
    asm volatile("ldmatrix.sync.aligned.m8n8.x2.shared.b16 {%0,%1}, [%2];" \
        : "=r"(r0), "=r"(r1) : "r"(addr))

__device__ __forceinline__ void mma16816(float* c, const uint32_t* a, uint32_t b0, uint32_t b1) {
    asm volatile(
        "mma.sync.aligned.m16n8k16.row.col.f32.bf16.bf16.f32 "
        "{%0,%1,%2,%3}, {%4,%5,%6,%7}, {%8,%9}, {%0,%1,%2,%3};"
        : "+f"(c[0]), "+f"(c[1]), "+f"(c[2]), "+f"(c[3])
        : "r"(a[0]), "r"(a[1]), "r"(a[2]), "r"(a[3]), "r"(b0), "r"(b1));
}

// ---------------- small kernels ----------------
__global__ void zero_stats_kernel() {
    int i = threadIdx.x;
    if (i < 3 * DDIM) { g_sum[i] = 0.f; g_sumsq[i] = 0.f; }
}

__global__ void finalize_stats_kernel(int layer, const float* __restrict__ g,
                                      const float* __restrict__ be) {
    int c = threadIdx.x;
    const float inv = 1.0f / (float)NROWS;
    float mu  = g_sum  [layer * DDIM + c] * inv;
    float var = g_sumsq[layer * DDIM + c] * inv - mu * mu;
    float s = rsqrtf(var + EPSV) * g[c];
    g_scale[layer * DDIM + c] = s;
    g_shift[layer * DDIM + c] = be[c] - mu * s;
}

__global__ void gather_split_kernel(const int* __restrict__ ids,
                                    const float* __restrict__ table) {
    int idx = blockIdx.x * blockDim.x + threadIdx.x;   // float4 index
    int row = idx >> 6;
    int q   = idx & 63;
    int src = ids[row];
    float4 v = reinterpret_cast<const float4*>(table + (size_t)src * DDIM)[q];
    __nv_bfloat16 h0, h1, h2, h3, l0, l1, l2, l3;
    split2(v.x, h0, l0); split2(v.y, h1, l1); split2(v.z, h2, l2); split2(v.w, h3, l3);
    reinterpret_cast<uint2*>(g_Xhi)[idx] = make_uint2(pack2(h0, h1), pack2(h2, h3));
    reinterpret_cast<uint2*>(g_Xlo)[idx] = make_uint2(pack2(l0, l1), pack2(l2, l3));
}

__global__ void prep_w_kernel(const float* __restrict__ W, const float* __restrict__ b,
                              int layer, int use_bn) {
    __shared__ float red[DDIM];
    int n = blockIdx.x, k = threadIdx.x;
    float w = W[k * DDIM + n];
    float s = 1.f, t = 0.f;
    if (use_bn) {
        s = g_scale[(layer - 1) * DDIM + k];
        t = g_shift[(layer - 1) * DDIM + k];
    }
    __nv_bfloat16 h, l;
    split2(w * s, h, l);
    g_Bhi[layer][n * DDIM + k] = h;
    g_Blo[layer][n * DDIM + k] = l;
    red[k] = t * w;
    __syncthreads();
    for (int st = 128; st > 0; st >>= 1) {
        if (k < st) red[k] += red[k + st];
        __syncthreads();
    }
    if (k == 0) g_bias[layer][n] = b[n] + red[0];
}

// ---------------- main fused GEMM layer (HMMA mma.sync, split-bf16 x3) ----------------
// CTA: M=128 x N=256, 8 warps (2M x 4N), warp tile 64x64. K chunks of 64, cp.async 2-stage.
template<int STATS, int FINAL>
__global__ __launch_bounds__(256, 1)
void gemm_kernel(const __nv_bfloat16* __restrict__ Ahi,
                 const __nv_bfloat16* __restrict__ Alo,
                 const __nv_bfloat16* __restrict__ Bhi,
                 const __nv_bfloat16* __restrict__ Blo,
                 const float* __restrict__ bias,
                 int layer,
                 float* __restrict__ outF,
                 __nv_bfloat16* __restrict__ outHi,
                 __nv_bfloat16* __restrict__ outLo)
{
    extern __shared__ char dyn_smem[];
    const int tid  = threadIdx.x;
    const int lane = tid & 31;
    const int wid  = tid >> 5;
    const int m_warp = (wid >> 2) * 64;
    const int n_warp = (wid & 3) * 64;
    const int r0 = blockIdx.x * 128;

    const uint32_t dyn0 = sm_u32(dyn_smem);
    const uint32_t su   = (dyn0 + 1023) & ~1023u;   // 1KB-aligned SMEM base

    float acc[4][8][4];
    #pragma unroll
    for (int i = 0; i < 4; i++)
        #pragma unroll
        for (int j = 0; j < 8; j++)
            #pragma unroll
            for (int q = 0; q < 4; q++) acc[i][j][q] = 0.f;

    // --- cp.async issue of one K-chunk into stage s ---
    auto issue = [&](int c) {
        const uint32_t sb = su + (c & 1) * STAGE_BYTES;
        const int kt = c * KC;
        #pragma unroll
        for (int i = 0; i < 4; i++) {           // A: 128 rows x 8 x 16B
            int idx = tid + i * 256;
            int row = idx >> 3, q = idx & 7;
            uint32_t sw = swz((uint32_t)(row * 128 + q * 16));
            const size_t g = (size_t)(r0 + row) * DDIM + kt + q * 8;
            CP16(sb + sw,         Ahi + g);
            CP16(sb + 16384 + sw, Alo + g);
        }
        #pragma unroll
        for (int i = 0; i < 8; i++) {           // B: 256 rows x 8 x 16B
            int idx = tid + i * 256;
            int row = idx >> 3, q = idx & 7;
            uint32_t sw = swz((uint32_t)(row * 128 + q * 16));
            const size_t g = (size_t)row * DDIM + kt + q * 8;
            CP16(sb + 32768 + sw, Bhi + g);
            CP16(sb + 65536 + sw, Blo + g);
        }
        CP_COMMIT();
    };

    issue(0);
    for (int c = 0; c < 4; c++) {
        __syncthreads();                 // nobody still reading the buffer we refill
        if (c < 3) { issue(c + 1); CP_WAIT1(); } else { CP_WAIT0(); }
        __syncthreads();                 // chunk c visible to all

        const uint32_t sa = su + (c & 1) * STAGE_BYTES;
        #pragma unroll
        for (int ks = 0; ks < 4; ks++) {
            uint32_t a_hi[4][4], a_lo[4][4];
            #pragma unroll
            for (int i = 0; i < 4; i++) {
                uint32_t off = (uint32_t)((m_warp + i * 16 + (lane & 15)) * 128
                                          + ks * 32 + (lane >> 4) * 16);
                uint32_t ad = sa + swz(off);
                LDSM_X4(a_hi[i], ad);
                LDSM_X4(a_lo[i], ad + 16384);
            }
            #pragma unroll
            for (int j = 0; j < 8; j++) {
                uint32_t offb = (uint32_t)((n_warp + j * 8 + (lane & 7)) * 128
                                           + ks * 32 + ((lane >> 3) & 1) * 16);
                uint32_t adb = sa + 32768 + swz(offb);
                uint32_t bh0, bh1, bl0, bl1;
                LDSM_X2(bh0, bh1, adb);
                LDSM_X2(bl0, bl1, adb + 32768);
                #pragma unroll
                for (int i = 0; i < 4; i++) {
                    mma16816(acc[i][j], a_hi[i], bh0, bh1);
                    mma16816(acc[i][j], a_hi[i], bl0, bl1);
                    mma16816(acc[i][j], a_lo[i], bh0, bh1);
                }
            }
        }
    }

    // ---- epilogue: bias + exact GELU + stores + column stats ----
    #pragma unroll
    for (int j = 0; j < 8; j++) {
        const int col0 = n_warp + j * 8 + (lane & 3) * 2;
        const float bi0 = bias[col0], bi1 = bias[col0 + 1];
        float su0 = 0.f, su1 = 0.f, sq0 = 0.f, sq1 = 0.f;
        #pragma unroll
        for (int i = 0; i < 4; i++) {
            const int rowA = r0 + m_warp + i * 16 + (lane >> 2);
            float v0 = gelu_exact(acc[i][j][0] + bi0);
            float v1 = gelu_exact(acc[i][j][1] + bi1);
            float v2 = gelu_exact(acc[i][j][2] + bi0);
            float v3 = gelu_exact(acc[i][j][3] + bi1);
            if (STATS) {
                su0 += v0 + v2; su1 += v1 + v3;
                sq0 += v0 * v0 + v2 * v2; sq1 += v1 * v1 + v3 * v3;
            }
            if (FINAL) {
                *reinterpret_cast<float2*>(outF + (size_t)rowA * DDIM + col0)
                    = make_float2(v0, v1);
                *reinterpret_cast<float2*>(outF + (size_t)(rowA + 8) * DDIM + col0)
                    = make_float2(v2, v3);
            } else {
                __nv_bfloat16 h0, l0, h1, l1;
                split2(v0, h0, l0); split2(v1, h1, l1);
                *reinterpret_cast<uint32_t*>(outHi + (size_t)rowA * DDIM + col0) = pack2(h0, h1);
                *reinterpret_cast<uint32_t*>(outLo + (size_t)rowA * DDIM + col0) = pack2(l0, l1);
                split2(v2, h0, l0); split2(v3, h1, l1);
                *reinterpret_cast<uint32_t*>(outHi + (size_t)(rowA + 8) * DDIM + col0) = pack2(h0, h1);
                *reinterpret_cast<uint32_t*>(outLo + (size_t)(rowA + 8) * DDIM + col0) = pack2(l0, l1);
            }
        }
        if (STATS) {
            #pragma unroll
            for (int m = 4; m <= 16; m <<= 1) {
                su0 += __shfl_xor_sync(0xFFFFFFFFu, su0, m);
                su1 += __shfl_xor_sync(0xFFFFFFFFu, su1, m);
                sq0 += __shfl_xor_sync(0xFFFFFFFFu, sq0, m);
                sq1 += __shfl_xor_sync(0xFFFFFFFFu, sq1, m);
            }
            if ((lane >> 2) == 0) {
                atomicAdd(&g_sum  [layer * DDIM + col0],     su0);
                atomicAdd(&g_sum  [layer * DDIM + col0 + 1], su1);
                atomicAdd(&g_sumsq[layer * DDIM + col0],     sq0);
                atomicAdd(&g_sumsq[layer * DDIM + col0 + 1], sq1);
            }
        }
    }
}

// ---------------- launch ----------------
extern "C" void kernel_launch(void* const* d_in, const int* in_sizes, int n_in,
                              void* d_out, int out_size) {
    const int*   ids   = (const int*)  d_in[0];
    const float* table = (const float*)d_in[1];
    const float* W[4]  = {(const float*)d_in[2], (const float*)d_in[4],
                          (const float*)d_in[6], (const float*)d_in[8]};
    const float* b[4]  = {(const float*)d_in[3], (const float*)d_in[5],
                          (const float*)d_in[7], (const float*)d_in[9]};
    const float* g[3]  = {(const float*)d_in[10], (const float*)d_in[12], (const float*)d_in[14]};
    const float* be[3] = {(const float*)d_in[11], (const float*)d_in[13], (const float*)d_in[15]};
    float* out = (float*)d_out;

    cudaFuncSetAttribute(gemm_kernel<1, 0>, cudaFuncAttributeMaxDynamicSharedMemorySize, SMEM_DYN);
    cudaFuncSetAttribute(gemm_kernel<0, 1>, cudaFuncAttributeMaxDynamicSharedMemorySize, SMEM_DYN);

    __nv_bfloat16 *Xhi, *Xlo, *Yhi, *Ylo, *Bh, *Bl;
    float *bs;
    cudaGetSymbolAddress((void**)&Xhi, g_Xhi);
    cudaGetSymbolAddress((void**)&Xlo, g_Xlo);
    cudaGetSymbolAddress((void**)&Yhi, g_Yhi);
    cudaGetSymbolAddress((void**)&Ylo, g_Ylo);
    cudaGetSymbolAddress((void**)&Bh,  g_Bhi);
    cudaGetSymbolAddress((void**)&Bl,  g_Blo);
    cudaGetSymbolAddress((void**)&bs,  g_bias);

    const dim3 grid(NROWS / 128), blk(256);

    zero_stats_kernel<<<1, 768>>>();
    gather_split_kernel<<<NROWS * DDIM / 4 / 256, 256>>>(ids, table);
    prep_w_kernel<<<DDIM, DDIM>>>(W[0], b[0], 0, 0);

    gemm_kernel<1, 0><<<grid, blk, SMEM_DYN>>>(
        Xhi, Xlo, Bh + 0 * DDIM * DDIM, Bl + 0 * DDIM * DDIM, bs + 0 * DDIM,
        0, nullptr, Yhi, Ylo);
    finalize_stats_kernel<<<1, DDIM>>>(0, g[0], be[0]);
    prep_w_kernel<<<DDIM, DDIM>>>(W[1], b[1], 1, 1);

    gemm_kernel<1, 0><<<grid, blk, SMEM_DYN>>>(
        Yhi, Ylo, Bh + 1 * DDIM * DDIM, Bl + 1 * DDIM * DDIM, bs + 1 * DDIM,
        1, nullptr, Xhi, Xlo);
    finalize_stats_kernel<<<1, DDIM>>>(1, g[1], be[1]);
    prep_w_kernel<<<DDIM, DDIM>>>(W[2], b[2], 2, 1);

    gemm_kernel<1, 0><<<grid, blk, SMEM_DYN>>>(
        Xhi, Xlo, Bh + 2 * DDIM * DDIM, Bl + 2 * DDIM * DDIM, bs + 2 * DDIM,
        2, nullptr, Yhi, Ylo);
    finalize_stats_kernel<<<1, DDIM>>>(2, g[2], be[2]);
    prep_w_kernel<<<DDIM, DDIM>>>(W[3], b[3], 3, 1);

    gemm_kernel<0, 1><<<grid, blk, SMEM_DYN>>>(
        Yhi, Ylo, Bh + 3 * DDIM * DDIM, Bl + 3 * DDIM * DDIM, bs + 3 * DDIM,
        3, out, nullptr, nullptr);
}